// round 6
// baseline (speedup 1.0000x reference)
#include <cuda_runtime.h>
#include <cuda_bf16.h>
#include <cstdint>
#include <math.h>

#define T_ 2032
#define TP_ 2048
#define D_ 1408
#define NH_ 1408
#define NHEADS_ 16
#define HD_ 88
#define HP_ 96
#define GK_ 1408
#define GN_ 1408
#define NCHUNK 88            // 1408 / 16

// Scratch (allocation-free rule: device globals)
__device__ __nv_bfloat16 g_xh[T_ * GK_], g_xl[T_ * GK_];      // x split (A operand)
__device__ __nv_bfloat16 g_ah[T_ * GK_], g_al[T_ * GK_];      // attn-out split
__device__ __nv_bfloat16 g_wh[4L * GK_ * GN_], g_wl[4L * GK_ * GN_];
// bf16 hi/lo split, rope-applied, padded to [2048][16][96]
#define PADSZ (TP_ * NHEADS_ * HP_)
__device__ __nv_bfloat16 g_qhi[PADSZ], g_qlo[PADSZ];
__device__ __nv_bfloat16 g_khi[PADSZ], g_klo[PADSZ];
__device__ __nv_bfloat16 g_vhi[PADSZ], g_vlo[PADSZ];

// ===========================================================================
// Helpers (baseline PTX — compute_103 safe)
// ===========================================================================
__device__ __forceinline__ uint32_t smem_u32(const void* p) {
    uint32_t a;
    asm("{ .reg .u64 t; cvta.to.shared.u64 t, %1; cvt.u32.u64 %0, t; }"
        : "=r"(a) : "l"(p));
    return a;
}
__device__ __forceinline__ void ldsm_x4(uint32_t* r, uint32_t addr) {
    asm volatile("ldmatrix.sync.aligned.m8n8.x4.shared.b16 {%0,%1,%2,%3}, [%4];"
                 : "=r"(r[0]), "=r"(r[1]), "=r"(r[2]), "=r"(r[3]) : "r"(addr));
}
__device__ __forceinline__ void ldsm_x4_t(uint32_t* r, uint32_t addr) {
    asm volatile("ldmatrix.sync.aligned.m8n8.x4.trans.shared.b16 {%0,%1,%2,%3}, [%4];"
                 : "=r"(r[0]), "=r"(r[1]), "=r"(r[2]), "=r"(r[3]) : "r"(addr));
}
__device__ __forceinline__ void mma_bf16(float* d, const uint32_t* a, const uint32_t* b) {
    asm volatile(
        "mma.sync.aligned.m16n8k16.row.col.f32.bf16.bf16.f32 "
        "{%0,%1,%2,%3}, {%4,%5,%6,%7}, {%8,%9}, {%0,%1,%2,%3};"
        : "+f"(d[0]), "+f"(d[1]), "+f"(d[2]), "+f"(d[3])
        : "r"(a[0]), "r"(a[1]), "r"(a[2]), "r"(a[3]), "r"(b[0]), "r"(b[1]));
}
__device__ __forceinline__ float ex2f(float x) {
    float y; asm("ex2.approx.f32 %0, %1;" : "=f"(y) : "f"(x)); return y;
}
__device__ __forceinline__ void cp16(uint32_t dst, const void* src) {
    asm volatile("cp.async.cg.shared.global [%0], [%1], 16;"
                 :: "r"(dst), "l"(src) : "memory");
}
__device__ __forceinline__ void cp16z(uint32_t dst, const void* src, uint32_t srcsz) {
    asm volatile("cp.async.cg.shared.global [%0], [%1], 16, %2;"
                 :: "r"(dst), "l"(src), "r"(srcsz) : "memory");
}
#define CP_COMMIT() asm volatile("cp.async.commit_group;" ::: "memory")
#define CP_WAIT(n)  asm volatile("cp.async.wait_group %0;" :: "n"(n) : "memory")

// split fp32 pair -> packed hi bf16x2, lo bf16x2
__device__ __forceinline__ void split2(float x, float y, uint32_t& h, uint32_t& l) {
    __nv_bfloat16 hx = __float2bfloat16_rn(x);
    __nv_bfloat16 hy = __float2bfloat16_rn(y);
    __nv_bfloat16 lx = __float2bfloat16_rn(x - __bfloat162float(hx));
    __nv_bfloat16 ly = __float2bfloat16_rn(y - __bfloat162float(hy));
    h = (uint32_t)__bfloat16_as_ushort(hx) | ((uint32_t)__bfloat16_as_ushort(hy) << 16);
    l = (uint32_t)__bfloat16_as_ushort(lx) | ((uint32_t)__bfloat16_as_ushort(ly) << 16);
}

// ===========================================================================
// Splits (pure bandwidth)
// ===========================================================================
__global__ void split_kernel(const float* __restrict__ src,
                             __nv_bfloat16* __restrict__ hi,
                             __nv_bfloat16* __restrict__ lo, int n2)
{
    int i = blockIdx.x * 256 + threadIdx.x;
    if (i >= n2) return;
    float2 v = ((const float2*)src)[i];
    uint32_t h, l;
    split2(v.x, v.y, h, l);
    ((uint32_t*)hi)[i] = h;
    ((uint32_t*)lo)[i] = l;
}

__global__ void wsplit_kernel(const float* __restrict__ w0, const float* __restrict__ w1,
                              const float* __restrict__ w2, const float* __restrict__ w3,
                              __nv_bfloat16* __restrict__ hi, __nv_bfloat16* __restrict__ lo)
{
    const int n2w = GK_ * GN_ / 2;
    long i = (long)blockIdx.x * 256 + threadIdx.x;
    if (i >= 4L * n2w) return;
    int which = (int)(i / n2w);
    long r = i - (long)which * n2w;
    const float* src = which == 0 ? w0 : which == 1 ? w1 : which == 2 ? w2 : w3;
    float2 v = ((const float2*)src)[r];
    uint32_t h, l;
    split2(v.x, v.y, h, l);
    ((uint32_t*)hi)[i] = h;
    ((uint32_t*)lo)[i] = l;
}

// zero pad regions of the 6 padded attention operand arrays
__global__ void pad_kernel(__nv_bfloat16* a0, __nv_bfloat16* a1, __nv_bfloat16* a2,
                           __nv_bfloat16* a3, __nv_bfloat16* a4, __nv_bfloat16* a5)
{
    int i = blockIdx.x * 256 + threadIdx.x;
    uint32_t idx;
    if (i < 131072) {                        // h in [88,96): 2048*16 pairs * 4 u32
        int th = i >> 2, off = i & 3;
        idx = (uint32_t)th * 48 + 44 + off;  // u32 index
    } else if (i < 131072 + 11264) {         // t in [2032,2048), h in [0,88)
        int j = i - 131072;
        int t = 2032 + j / (16 * 44);
        int r = j % (16 * 44);
        int head = r / 44, p = r % 44;
        idx = (uint32_t)(t * 16 + head) * 48 + p;
    } else return;
    ((uint32_t*)a0)[idx] = 0; ((uint32_t*)a1)[idx] = 0;
    ((uint32_t*)a2)[idx] = 0; ((uint32_t*)a3)[idx] = 0;
    ((uint32_t*)a4)[idx] = 0; ((uint32_t*)a5)[idx] = 0;
}

// ===========================================================================
// HMMA GEMM v3: bf16 hi/lo in, 3-stage cp.async pipeline, fused N-groups,
// fused epilogue (mode 0: RoPE+split+pad for QKV; mode 1: fp32 C + bias).
// 128x128 CTA tile, BK=16, 8 warps x (32x64), 3-term split, fp32 accum.
// ===========================================================================
struct G3 {
    const __nv_bfloat16* bh[3];
    const __nv_bfloat16* bl[3];
    const float* bias[3];
    __nv_bfloat16* ohi[3];
    __nv_bfloat16* olo[3];
    float* c0;
    int mode;          // 0 = QKV fused epilogue, 1 = plain fp32 C
};

#define AS_ST 24        // bf16 per A smem row (48 B)
#define BS_ST 136       // bf16 per B smem row (272 B)
#define A_STAGE 12288   // bytes per A stage (hi+lo)
#define B_STAGE 8704    // bytes per B stage (hi+lo)
#define B_BASE  36864   // 3 * A_STAGE
#define GEMM_SMEM (B_BASE + 3 * B_STAGE)   // 62976

__global__ __launch_bounds__(256, 2)
void hmma_gemm3_kernel(const __nv_bfloat16* __restrict__ Ah,
                       const __nv_bfloat16* __restrict__ Al,
                       const float* __restrict__ fc, G3 g)
{
    extern __shared__ char smg[];
    uint32_t sb = smem_u32(smg);

    const int tid = threadIdx.x;
    const int wid = tid >> 5, lane = tid & 31;
    const int wm = wid & 3, wn = wid >> 2;
    const int bm = blockIdx.y * 128;
    const int which = blockIdx.x / 11;
    const int bn = (blockIdx.x - which * 11) * 128;

    const int arow = tid >> 1;
    const int acs = (tid & 1) * 8;
    const int brow = tid >> 4;
    const int bcs = (tid & 15) * 8;
    const uint32_t aok = ((bm + arow) < T_) ? 16u : 0u;

    const __nv_bfloat16* agh = Ah + (long)(bm + arow) * GK_ + acs;
    const __nv_bfloat16* agl = Al + (long)(bm + arow) * GK_ + acs;
    const __nv_bfloat16* bgh = g.bh[which] + (long)brow * GN_ + bn + bcs;
    const __nv_bfloat16* bgl = g.bl[which] + (long)brow * GN_ + bn + bcs;

    const uint32_t as0 = sb + (arow * AS_ST + acs) * 2;
    const uint32_t as1 = as0 + 6144;
    const uint32_t bs0 = sb + B_BASE + (brow * BS_ST + bcs) * 2;
    const uint32_t bs1 = bs0 + 4352;

    float acc[2][8][4];
#pragma unroll
    for (int i = 0; i < 2; i++)
#pragma unroll
        for (int j = 0; j < 8; j++)
#pragma unroll
            for (int e = 0; e < 4; e++) acc[i][j][e] = 0.f;

    // prologue: stages 0,1
#pragma unroll
    for (int c = 0; c < 2; c++) {
        cp16z(as0 + c * A_STAGE, agh + c * 16, aok);
        cp16z(as1 + c * A_STAGE, agl + c * 16, aok);
        cp16(bs0 + c * B_STAGE, bgh + (long)c * 16 * GN_);
        cp16(bs1 + c * B_STAGE, bgl + (long)c * 16 * GN_);
        CP_COMMIT();
    }

    for (int c = 0; c < NCHUNK; c++) {
        const int s = c % 3;
        if (c == NCHUNK - 1) { CP_WAIT(0); } else { CP_WAIT(1); }
        __syncthreads();

        if (c + 2 < NCHUNK) {
            const int ns = (c + 2) % 3;
            cp16z(as0 + ns * A_STAGE, agh + (c + 2) * 16, aok);
            cp16z(as1 + ns * A_STAGE, agl + (c + 2) * 16, aok);
            cp16(bs0 + ns * B_STAGE, bgh + (long)(c + 2) * 16 * GN_);
            cp16(bs1 + ns * B_STAGE, bgl + (long)(c + 2) * 16 * GN_);
            CP_COMMIT();
        }

        uint32_t ah[2][4], al[2][4], bh[4][4], bl[4][4];
        {
            uint32_t a_hi = sb + s * A_STAGE;
            uint32_t a_lo = a_hi + 6144;
            uint32_t aoff = (uint32_t)((wm * 32 + (lane & 15)) * 48 + (lane >> 4) * 16);
#pragma unroll
            for (int i = 0; i < 2; i++) {
                ldsm_x4(ah[i], a_hi + aoff + i * 16 * 48);
                ldsm_x4(al[i], a_lo + aoff + i * 16 * 48);
            }
            uint32_t b_hi = sb + B_BASE + s * B_STAGE;
            uint32_t b_lo = b_hi + 4352;
            uint32_t boff = (uint32_t)((lane & 15) * 272 + wn * 128 + (lane >> 4) * 16);
#pragma unroll
            for (int j2 = 0; j2 < 4; j2++) {
                ldsm_x4_t(bh[j2], b_hi + boff + j2 * 32);
                ldsm_x4_t(bl[j2], b_lo + boff + j2 * 32);
            }
        }
#pragma unroll
        for (int i = 0; i < 2; i++)
#pragma unroll
            for (int j = 0; j < 8; j++) {
                const uint32_t* bph = &bh[j >> 1][(j & 1) * 2];
                const uint32_t* bpl = &bl[j >> 1][(j & 1) * 2];
                mma_bf16(acc[i][j], ah[i], bph);
                mma_bf16(acc[i][j], ah[i], bpl);
                mma_bf16(acc[i][j], al[i], bph);
            }
    }

    // ---- epilogue ----
    const float* bias = g.bias[which];
    if (g.mode == 1) {
        float* C = g.c0;
#pragma unroll
        for (int i = 0; i < 2; i++) {
            int r0 = bm + wm * 32 + i * 16 + (lane >> 2);
#pragma unroll
            for (int j = 0; j < 8; j++) {
                int cc = bn + wn * 64 + j * 8 + (lane & 3) * 2;
                float b0 = bias[cc], b1 = bias[cc + 1];
                if (r0 < T_) {
                    float* p = C + (long)r0 * GN_ + cc;
                    p[0] = acc[i][j][0] + b0;
                    p[1] = acc[i][j][1] + b1;
                }
                if (r0 + 8 < T_) {
                    float* p = C + (long)(r0 + 8) * GN_ + cc;
                    p[0] = acc[i][j][2] + b0;
                    p[1] = acc[i][j][3] + b1;
                }
            }
        }
    } else {
        __nv_bfloat16* ohi = g.ohi[which];
        __nv_bfloat16* olo = g.olo[which];
        const bool dorope = (which < 2);
#pragma unroll
        for (int i = 0; i < 2; i++) {
            int r0 = bm + wm * 32 + i * 16 + (lane >> 2);
#pragma unroll
            for (int j = 0; j < 8; j++) {
                int cc = bn + wn * 64 + j * 8 + (lane & 3) * 2;
                float b0 = bias[cc], b1 = bias[cc + 1];
                int head = cc / HD_;
                int h = cc - head * HD_;       // even, h+1 same head
#pragma unroll
                for (int half = 0; half < 2; half++) {
                    int t = r0 + half * 8;
                    if (t >= T_) continue;
                    float v0 = acc[i][j][2 * half + 0] + b0;
                    float v1 = acc[i][j][2 * half + 1] + b1;
                    float r0v = v0, r1v = v1;
                    if (dorope) {
                        float cs = fc[t * HD_ + h];
                        float sn = fc[t * HD_ + h + 1];
                        r0v = v0 * cs - v1 * sn;
                        r1v = v0 * sn + v1 * cs;
                    }
                    uint32_t hh, ll;
                    split2(r0v, r1v, hh, ll);
                    uint32_t dst = (uint32_t)(t * 16 + head) * HP_ + h;
                    *(uint32_t*)(ohi + dst) = hh;
                    *(uint32_t*)(olo + dst) = ll;
                }
            }
        }
    }
}

// ===========================================================================
// HMMA flash attention — writes hi/lo bf16 split output directly.
// ===========================================================================
#define ATT_SMEM 106496
#define SSTB 208
#define ARRB 13312
#define BUFB 53248

__global__ __launch_bounds__(256, 1)
void hmma_attn_kernel(const __nv_bfloat16* __restrict__ qhi, const __nv_bfloat16* __restrict__ qlo,
                      const __nv_bfloat16* __restrict__ khi, const __nv_bfloat16* __restrict__ klo,
                      const __nv_bfloat16* __restrict__ vhi, const __nv_bfloat16* __restrict__ vlo,
                      __nv_bfloat16* __restrict__ Oh, __nv_bfloat16* __restrict__ Ol)
{
    extern __shared__ char sm[];
    uint32_t sbase = smem_u32(sm);
    const int tid = threadIdx.x;
    const int wid = tid >> 5;
    const int lane = tid & 31;
    const int n = blockIdx.y;
    const int q0 = blockIdx.x * 128;
    const float sl2 = 0.15379179f;    // 88^-0.5 * log2(e)

#pragma unroll
    for (int it = 0; it < 12; it++) {
        int id = tid + it * 256;
        int arr = id / 1536;
        int rem = id - arr * 1536;
        int row = rem / 12;
        int c   = rem - row * 12;
        const __nv_bfloat16* src = (arr ? qlo : qhi) + ((long)(q0 + row) * 16 + n) * 96 + c * 8;
        cp16(sbase + arr * 26624 + row * SSTB + c * 16, src);
    }
    CP_COMMIT();
    CP_WAIT(0);
    __syncthreads();

    uint32_t qh[6][4], ql[6][4];
    {
        uint32_t qaddr = sbase + (wid * 16 + (lane & 15)) * SSTB + (lane >> 4) * 16;
#pragma unroll
        for (int kk = 0; kk < 6; kk++) {
            ldsm_x4(qh[kk], qaddr + kk * 32);
            ldsm_x4(ql[kk], qaddr + 26624 + kk * 32);
        }
    }
    __syncthreads();

    float mstat[2] = {-1e30f, -1e30f};
    float lstat[2] = {0.f, 0.f};
    float oacc[12][4];
#pragma unroll
    for (int f = 0; f < 12; f++)
#pragma unroll
        for (int e = 0; e < 4; e++) oacc[f][e] = 0.f;

#pragma unroll
    for (int it = 0; it < 12; it++) {
        int id = tid + it * 256;
        int arr = id / 768;
        int rem = id - arr * 768;
        int row = rem / 12;
        int c   = rem - row * 12;
        const __nv_bfloat16* src =
            (arr == 0 ? khi : arr == 1 ? klo : arr == 2 ? vhi : vlo)
            + ((long)row * 16 + n) * 96 + c * 8;
        cp16(sbase + arr * ARRB + row * SSTB + c * 16, src);
    }
    CP_COMMIT();

    for (int bi = 0; bi < 32; bi++) {
        const int buf = bi & 1;
        if (bi + 1 < 32) {
#pragma unroll
            for (int it = 0; it < 12; it++) {
                int id = tid + it * 256;
                int arr = id / 768;
                int rem = id - arr * 768;
                int row = rem / 12;
                int c   = rem - row * 12;
                const __nv_bfloat16* src =
                    (arr == 0 ? khi : arr == 1 ? klo : arr == 2 ? vhi : vlo)
                    + ((long)((bi + 1) * 64 + row) * 16 + n) * 96 + c * 8;
                cp16(sbase + (1 - buf) * BUFB + arr * ARRB + row * SSTB + c * 16, src);
            }
            CP_COMMIT();
            CP_WAIT(1);
        } else {
            CP_WAIT(0);
        }
        __syncthreads();

        float sacc[8][4];
#pragma unroll
        for (int f = 0; f < 8; f++)
#pragma unroll
            for (int e = 0; e < 4; e++) sacc[f][e] = 0.f;

        uint32_t kb = sbase + buf * BUFB;
#pragma unroll
        for (int kk = 0; kk < 6; kk++) {
            uint32_t ka = kb + (lane & 15) * SSTB + (lane >> 4) * 16 + kk * 32;
#pragma unroll
            for (int j2 = 0; j2 < 4; j2++) {
                uint32_t rh[4], rl[4];
                ldsm_x4(rh, ka + j2 * (16 * SSTB));
                ldsm_x4(rl, ka + ARRB + j2 * (16 * SSTB));
                uint32_t b0h[2] = {rh[0], rh[2]}, b1h[2] = {rh[1], rh[3]};
                uint32_t b0l[2] = {rl[0], rl[2]}, b1l[2] = {rl[1], rl[3]};
                mma_bf16(sacc[2 * j2],     qh[kk], b0h);
                mma_bf16(sacc[2 * j2],     qh[kk], b0l);
                mma_bf16(sacc[2 * j2],     ql[kk], b0h);
                mma_bf16(sacc[2 * j2 + 1], qh[kk], b1h);
                mma_bf16(sacc[2 * j2 + 1], qh[kk], b1l);
                mma_bf16(sacc[2 * j2 + 1], ql[kk], b1h);
            }
        }

#pragma unroll
        for (int f = 0; f < 8; f++)
#pragma unroll
            for (int e = 0; e < 4; e++) sacc[f][e] *= sl2;
        if (bi == 31) {
#pragma unroll
            for (int e = 0; e < 4; e++) { sacc[6][e] = -1e30f; sacc[7][e] = -1e30f; }
        }

        float mxA = -1e30f, mxB = -1e30f;
#pragma unroll
        for (int f = 0; f < 8; f++) {
            mxA = fmaxf(mxA, fmaxf(sacc[f][0], sacc[f][1]));
            mxB = fmaxf(mxB, fmaxf(sacc[f][2], sacc[f][3]));
        }
        mxA = fmaxf(mxA, __shfl_xor_sync(0xffffffffu, mxA, 1));
        mxA = fmaxf(mxA, __shfl_xor_sync(0xffffffffu, mxA, 2));
        mxB = fmaxf(mxB, __shfl_xor_sync(0xffffffffu, mxB, 1));
        mxB = fmaxf(mxB, __shfl_xor_sync(0xffffffffu, mxB, 2));
        float mA = fmaxf(mstat[0], mxA);
        float mB = fmaxf(mstat[1], mxB);
        float corrA = ex2f(mstat[0] - mA);
        float corrB = ex2f(mstat[1] - mB);
        mstat[0] = mA; mstat[1] = mB;

        float rsA = 0.f, rsB = 0.f;
#pragma unroll
        for (int f = 0; f < 8; f++) {
            sacc[f][0] = ex2f(sacc[f][0] - mA);
            sacc[f][1] = ex2f(sacc[f][1] - mA);
            sacc[f][2] = ex2f(sacc[f][2] - mB);
            sacc[f][3] = ex2f(sacc[f][3] - mB);
            rsA += sacc[f][0] + sacc[f][1];
            rsB += sacc[f][2] + sacc[f][3];
        }
        rsA += __shfl_xor_sync(0xffffffffu, rsA, 1);
        rsA += __shfl_xor_sync(0xffffffffu, rsA, 2);
        rsB += __shfl_xor_sync(0xffffffffu, rsB, 1);
        rsB += __shfl_xor_sync(0xffffffffu, rsB, 2);
        lstat[0] = lstat[0] * corrA + rsA;
        lstat[1] = lstat[1] * corrB + rsB;
#pragma unroll
        for (int f = 0; f < 12; f++) {
            oacc[f][0] *= corrA; oacc[f][1] *= corrA;
            oacc[f][2] *= corrB; oacc[f][3] *= corrB;
        }

        uint32_t vbh = kb + 2 * ARRB;
#pragma unroll
        for (int kk = 0; kk < 4; kk++) {
            uint32_t phi[4], plo[4];
            split2(sacc[2 * kk][0],     sacc[2 * kk][1],     phi[0], plo[0]);
            split2(sacc[2 * kk][2],     sacc[2 * kk][3],     phi[1], plo[1]);
            split2(sacc[2 * kk + 1][0], sacc[2 * kk + 1][1], phi[2], plo[2]);
            split2(sacc[2 * kk + 1][2], sacc[2 * kk + 1][3], phi[3], plo[3]);

            uint32_t va = vbh + (kk * 16 + (lane & 15)) * SSTB + (lane >> 4) * 16;
#pragma unroll
            for (int j2 = 0; j2 < 6; j2++) {
                uint32_t th[4], tl[4];
                ldsm_x4_t(th, va + j2 * 32);
                ldsm_x4_t(tl, va + ARRB + j2 * 32);
                mma_bf16(oacc[2 * j2],     phi, &th[0]);
                mma_bf16(oacc[2 * j2],     phi, &tl[0]);
                mma_bf16(oacc[2 * j2],     plo, &th[0]);
                mma_bf16(oacc[2 * j2 + 1], phi, &th[2]);
                mma_bf16(oacc[2 * j2 + 1], phi, &tl[2]);
                mma_bf16(oacc[2 * j2 + 1], plo, &th[2]);
            }
        }
        __syncthreads();
    }

    float invA = 1.f / lstat[0];
    float invB = 1.f / lstat[1];
    int rA = q0 + wid * 16 + (lane >> 2);
    int rB = rA + 8;
#pragma unroll
    for (int f = 0; f < 11; f++) {
        int h = n * HD_ + f * 8 + (lane & 3) * 2;
        uint32_t hh, ll;
        if (rA < T_) {
            split2(oacc[f][0] * invA, oacc[f][1] * invA, hh, ll);
            *(uint32_t*)(Oh + (long)rA * NH_ + h) = hh;
            *(uint32_t*)(Ol + (long)rA * NH_ + h) = ll;
        }
        if (rB < T_) {
            split2(oacc[f][2] * invB, oacc[f][3] * invB, hh, ll);
            *(uint32_t*)(Oh + (long)rB * NH_ + h) = hh;
            *(uint32_t*)(Ol + (long)rB * NH_ + h) = ll;
        }
    }
}

// ---------------------------------------------------------------------------
extern "C" void kernel_launch(void* const* d_in, const int* in_sizes, int n_in,
                              void* d_out, int out_size)
{
    const float* x  = (const float*)d_in[0];
    const float* fc = (const float*)d_in[1];
    const float* Wq = (const float*)d_in[2];
    const float* bq = (const float*)d_in[3];
    const float* Wk = (const float*)d_in[4];
    const float* bk = (const float*)d_in[5];
    const float* Wv = (const float*)d_in[6];
    const float* bv = (const float*)d_in[7];
    const float* Wo = (const float*)d_in[8];
    const float* bo = (const float*)d_in[9];
    float* out = (float*)d_out;

    __nv_bfloat16 *xh, *xl, *ah, *al, *wh, *wl;
    __nv_bfloat16 *qhi, *qlo, *khi, *klo, *vhi, *vlo;
    cudaGetSymbolAddress((void**)&xh, g_xh);
    cudaGetSymbolAddress((void**)&xl, g_xl);
    cudaGetSymbolAddress((void**)&ah, g_ah);
    cudaGetSymbolAddress((void**)&al, g_al);
    cudaGetSymbolAddress((void**)&wh, g_wh);
    cudaGetSymbolAddress((void**)&wl, g_wl);
    cudaGetSymbolAddress((void**)&qhi, g_qhi);
    cudaGetSymbolAddress((void**)&qlo, g_qlo);
    cudaGetSymbolAddress((void**)&khi, g_khi);
    cudaGetSymbolAddress((void**)&klo, g_klo);
    cudaGetSymbolAddress((void**)&vhi, g_vhi);
    cudaGetSymbolAddress((void**)&vlo, g_vlo);

    const long WSZ = (long)GK_ * GN_;
    const int n2x = T_ * GK_ / 2;
    const long n4w = 4L * WSZ / 2;

    // pad-zero + splits
    pad_kernel<<<(131072 + 11264 + 255) / 256, 256>>>(qhi, qlo, khi, klo, vhi, vlo);
    split_kernel<<<(n2x + 255) / 256, 256>>>(x, xh, xl, n2x);
    wsplit_kernel<<<(int)((n4w + 255) / 256), 256>>>(Wq, Wk, Wv, Wo, wh, wl);

    cudaFuncSetAttribute(hmma_gemm3_kernel,
                         cudaFuncAttributeMaxDynamicSharedMemorySize, GEMM_SMEM);
    cudaFuncSetAttribute(hmma_attn_kernel,
                         cudaFuncAttributeMaxDynamicSharedMemorySize, ATT_SMEM);

    // fused QKV GEMM + RoPE + split + pad epilogue (grid 33x16)
    G3 gq;
    gq.bh[0] = wh + 0 * WSZ; gq.bl[0] = wl + 0 * WSZ; gq.bias[0] = bq;
    gq.bh[1] = wh + 1 * WSZ; gq.bl[1] = wl + 1 * WSZ; gq.bias[1] = bk;
    gq.bh[2] = wh + 2 * WSZ; gq.bl[2] = wl + 2 * WSZ; gq.bias[2] = bv;
    gq.ohi[0] = qhi; gq.olo[0] = qlo;
    gq.ohi[1] = khi; gq.olo[1] = klo;
    gq.ohi[2] = vhi; gq.olo[2] = vlo;
    gq.c0 = nullptr; gq.mode = 0;
    hmma_gemm3_kernel<<<dim3(33, 16), 256, GEMM_SMEM>>>(xh, xl, fc, gq);

    // HMMA flash attention -> split output
    hmma_attn_kernel<<<dim3(16, 16), 256, ATT_SMEM>>>(qhi, qlo, khi, klo,
                                                      vhi, vlo, ah, al);

    // out-proj (mode 1)
    G3 go;
    go.bh[0] = wh + 3 * WSZ; go.bl[0] = wl + 3 * WSZ; go.bias[0] = bo;
    go.bh[1] = go.bh[0]; go.bl[1] = go.bl[0]; go.bias[1] = bo;
    go.bh[2] = go.bh[0]; go.bl[2] = go.bl[0]; go.bias[2] = bo;
    go.ohi[0] = go.ohi[1] = go.ohi[2] = nullptr;
    go.olo[0] = go.olo[1] = go.olo[2] = nullptr;
    go.c0 = out; go.mode = 1;
    hmma_gemm3_kernel<<<dim3(11, 16), 256, GEMM_SMEM>>>(ah, al, fc, go);
}

// round 7
// speedup vs baseline: 1.0159x; 1.0159x over previous
#include <cuda_runtime.h>
#include <cuda_bf16.h>
#include <cstdint>
#include <math.h>

#define T_ 2032
#define TP_ 2048
#define TKV_ 2112            // keys padded to 22 * 96
#define D_ 1408
#define NH_ 1408
#define NHEADS_ 16
#define HD_ 88
#define HP_ 96
#define GK_ 1408
#define GN_ 1408
#define NC2 44               // 1408 / 32

// Scratch (allocation-free rule: device globals)
__device__ __nv_bfloat16 g_xh[T_ * GK_], g_xl[T_ * GK_];      // x split (A operand)
__device__ __nv_bfloat16 g_ah[T_ * GK_], g_al[T_ * GK_];      // attn-out split
__device__ __nv_bfloat16 g_wh[4L * GK_ * GN_], g_wl[4L * GK_ * GN_];
// bf16 hi/lo split, rope-applied, padded to [2112][16][96]
#define PADSZ (TKV_ * NHEADS_ * HP_)
__device__ __nv_bfloat16 g_qhi[PADSZ], g_qlo[PADSZ];
__device__ __nv_bfloat16 g_khi[PADSZ], g_klo[PADSZ];
__device__ __nv_bfloat16 g_vhi[PADSZ], g_vlo[PADSZ];

// ===========================================================================
// Helpers (baseline PTX — compute_103 safe)
// ===========================================================================
__device__ __forceinline__ uint32_t smem_u32(const void* p) {
    uint32_t a;
    asm("{ .reg .u64 t; cvta.to.shared.u64 t, %1; cvt.u32.u64 %0, t; }"
        : "=r"(a) : "l"(p));
    return a;
}
__device__ __forceinline__ void ldsm_x4(uint32_t* r, uint32_t addr) {
    asm volatile("ldmatrix.sync.aligned.m8n8.x4.shared.b16 {%0,%1,%2,%3}, [%4];"
                 : "=r"(r[0]), "=r"(r[1]), "=r"(r[2]), "=r"(r[3]) : "r"(addr));
}
__device__ __forceinline__ void ldsm_x4_t(uint32_t* r, uint32_t addr) {
    asm volatile("ldmatrix.sync.aligned.m8n8.x4.trans.shared.b16 {%0,%1,%2,%3}, [%4];"
                 : "=r"(r[0]), "=r"(r[1]), "=r"(r[2]), "=r"(r[3]) : "r"(addr));
}
__device__ __forceinline__ void mma_bf16(float* d, const uint32_t* a, const uint32_t* b) {
    asm volatile(
        "mma.sync.aligned.m16n8k16.row.col.f32.bf16.bf16.f32 "
        "{%0,%1,%2,%3}, {%4,%5,%6,%7}, {%8,%9}, {%0,%1,%2,%3};"
        : "+f"(d[0]), "+f"(d[1]), "+f"(d[2]), "+f"(d[3])
        : "r"(a[0]), "r"(a[1]), "r"(a[2]), "r"(a[3]), "r"(b[0]), "r"(b[1]));
}
__device__ __forceinline__ float ex2f(float x) {
    float y; asm("ex2.approx.f32 %0, %1;" : "=f"(y) : "f"(x)); return y;
}
__device__ __forceinline__ void cp16(uint32_t dst, const void* src) {
    asm volatile("cp.async.cg.shared.global [%0], [%1], 16;"
                 :: "r"(dst), "l"(src) : "memory");
}
__device__ __forceinline__ void cp16z(uint32_t dst, const void* src, uint32_t srcsz) {
    asm volatile("cp.async.cg.shared.global [%0], [%1], 16, %2;"
                 :: "r"(dst), "l"(src), "r"(srcsz) : "memory");
}
#define CP_COMMIT() asm volatile("cp.async.commit_group;" ::: "memory")
#define CP_WAIT(n)  asm volatile("cp.async.wait_group %0;" :: "n"(n) : "memory")

// split fp32 pair -> packed hi bf16x2, lo bf16x2
__device__ __forceinline__ void split2(float x, float y, uint32_t& h, uint32_t& l) {
    __nv_bfloat16 hx = __float2bfloat16_rn(x);
    __nv_bfloat16 hy = __float2bfloat16_rn(y);
    __nv_bfloat16 lx = __float2bfloat16_rn(x - __bfloat162float(hx));
    __nv_bfloat16 ly = __float2bfloat16_rn(y - __bfloat162float(hy));
    h = (uint32_t)__bfloat16_as_ushort(hx) | ((uint32_t)__bfloat16_as_ushort(hy) << 16);
    l = (uint32_t)__bfloat16_as_ushort(lx) | ((uint32_t)__bfloat16_as_ushort(ly) << 16);
}

// ===========================================================================
// Splits (pure bandwidth)
// ===========================================================================
__global__ void split_kernel(const float* __restrict__ src,
                             __nv_bfloat16* __restrict__ hi,
                             __nv_bfloat16* __restrict__ lo, int n2)
{
    int i = blockIdx.x * 256 + threadIdx.x;
    if (i >= n2) return;
    float2 v = ((const float2*)src)[i];
    uint32_t h, l;
    split2(v.x, v.y, h, l);
    ((uint32_t*)hi)[i] = h;
    ((uint32_t*)lo)[i] = l;
}

__global__ void wsplit_kernel(const float* __restrict__ w0, const float* __restrict__ w1,
                              const float* __restrict__ w2, const float* __restrict__ w3,
                              __nv_bfloat16* __restrict__ hi, __nv_bfloat16* __restrict__ lo)
{
    const int n2w = GK_ * GN_ / 2;
    long i = (long)blockIdx.x * 256 + threadIdx.x;
    if (i >= 4L * n2w) return;
    int which = (int)(i / n2w);
    long r = i - (long)which * n2w;
    const float* src = which == 0 ? w0 : which == 1 ? w1 : which == 2 ? w2 : w3;
    float2 v = ((const float2*)src)[r];
    uint32_t h, l;
    split2(v.x, v.y, h, l);
    ((uint32_t*)hi)[i] = h;
    ((uint32_t*)lo)[i] = l;
}

// zero pad regions of the 6 padded attention operand arrays
// region1: h-pairs [44,48) for all 2112*16 row-heads (u32 idx)
// region2: t in [2032,2112), h-pairs [0,44)
#define PAD_R1 (TKV_ * NHEADS_ * 4)
#define PAD_R2 ((TKV_ - T_) * NHEADS_ * 44)
__global__ void pad_kernel(__nv_bfloat16* a0, __nv_bfloat16* a1, __nv_bfloat16* a2,
                           __nv_bfloat16* a3, __nv_bfloat16* a4, __nv_bfloat16* a5)
{
    int i = blockIdx.x * 256 + threadIdx.x;
    uint32_t idx;
    if (i < PAD_R1) {
        int th = i >> 2, off = i & 3;
        idx = (uint32_t)th * 48 + 44 + off;
    } else if (i < PAD_R1 + PAD_R2) {
        int j = i - PAD_R1;
        int t = T_ + j / (NHEADS_ * 44);
        int r = j % (NHEADS_ * 44);
        int head = r / 44, p = r % 44;
        idx = (uint32_t)(t * NHEADS_ + head) * 48 + p;
    } else return;
    ((uint32_t*)a0)[idx] = 0; ((uint32_t*)a1)[idx] = 0;
    ((uint32_t*)a2)[idx] = 0; ((uint32_t*)a3)[idx] = 0;
    ((uint32_t*)a4)[idx] = 0; ((uint32_t*)a5)[idx] = 0;
}

// ===========================================================================
// HMMA GEMM v4: BK=32 macro-chunks (2 x k16 sub-steps), 2-stage pipeline,
// ONE bar + ONE wait per macro-chunk. bf16 hi/lo 3-term, fp32 accum.
// 128x128 CTA tile, 8 warps x (32x64). Fused N-groups + fused epilogues.
// ===========================================================================
struct G3 {
    const __nv_bfloat16* bh[3];
    const __nv_bfloat16* bl[3];
    const float* bias[3];
    __nv_bfloat16* ohi[3];
    __nv_bfloat16* olo[3];
    float* c0;
    int mode;          // 0 = QKV fused epilogue, 1 = plain fp32 C
};

#define AS_ST 24        // bf16 per A smem row (48 B)
#define BS_ST 136       // bf16 per B smem row (272 B)
#define SUBA  12288     // A hi+lo bytes per k16 sub-chunk
#define SUBB  8704      // B hi+lo bytes per k16 sub-chunk
#define BBASE 24576     // 2*SUBA
#define STAGE 41984     // BBASE + 2*SUBB
#define GEMM_SMEM (2 * STAGE)   // 83968

__global__ __launch_bounds__(256, 2)
void hmma_gemm4_kernel(const __nv_bfloat16* __restrict__ Ah,
                       const __nv_bfloat16* __restrict__ Al,
                       const float* __restrict__ fc, G3 g)
{
    extern __shared__ char smg[];
    uint32_t sb = smem_u32(smg);

    const int tid = threadIdx.x;
    const int wid = tid >> 5, lane = tid & 31;
    const int wm = wid & 3, wn = wid >> 2;
    const int bm = blockIdx.y * 128;
    const int which = blockIdx.x / 11;
    const int bn = (blockIdx.x - which * 11) * 128;

    const int arow = tid >> 1;
    const int acs = (tid & 1) * 8;
    const int brow = tid >> 4;
    const int bcs = (tid & 15) * 8;
    const uint32_t aok = ((bm + arow) < T_) ? 16u : 0u;

    const __nv_bfloat16* agh = Ah + (long)(bm + arow) * GK_ + acs;
    const __nv_bfloat16* agl = Al + (long)(bm + arow) * GK_ + acs;
    const __nv_bfloat16* bgh = g.bh[which] + (long)brow * GN_ + bn + bcs;
    const __nv_bfloat16* bgl = g.bl[which] + (long)brow * GN_ + bn + bcs;

    const uint32_t as0 = sb + (arow * AS_ST + acs) * 2;
    const uint32_t bs0 = sb + BBASE + (brow * BS_ST + bcs) * 2;

    float acc[2][8][4];
#pragma unroll
    for (int i = 0; i < 2; i++)
#pragma unroll
        for (int j = 0; j < 8; j++)
#pragma unroll
            for (int e = 0; e < 4; e++) acc[i][j][e] = 0.f;

    const uint32_t aoff = (uint32_t)((wm * 32 + (lane & 15)) * 48 + (lane >> 4) * 16);
    const uint32_t boff = (uint32_t)((lane & 15) * 272 + wn * 128 + (lane >> 4) * 16);

    // prologue: macro-chunk 0 -> stage 0
#pragma unroll
    for (int u = 0; u < 2; u++) {
        cp16z(as0 + u * SUBA, agh + u * 16, aok);
        cp16z(as0 + u * SUBA + 6144, agl + u * 16, aok);
        cp16(bs0 + u * SUBB, bgh + (long)(u * 16) * GN_);
        cp16(bs0 + u * SUBB + 4352, bgl + (long)(u * 16) * GN_);
    }
    CP_COMMIT();

    for (int c = 0; c < NC2; c++) {
        const int s = c & 1;
        CP_WAIT(0);
        __syncthreads();

        if (c + 1 < NC2) {
            const uint32_t st = (uint32_t)((1 - s) * STAGE);
            const int k0 = (c + 1) * 32;
#pragma unroll
            for (int u = 0; u < 2; u++) {
                cp16z(as0 + st + u * SUBA, agh + k0 + u * 16, aok);
                cp16z(as0 + st + u * SUBA + 6144, agl + k0 + u * 16, aok);
                cp16(bs0 + st + u * SUBB, bgh + (long)(k0 + u * 16) * GN_);
                cp16(bs0 + st + u * SUBB + 4352, bgl + (long)(k0 + u * 16) * GN_);
            }
            CP_COMMIT();
        }

#pragma unroll
        for (int u = 0; u < 2; u++) {
            uint32_t ah[2][4], al[2][4], bh[4][4], bl[4][4];
            uint32_t a_hi = sb + s * STAGE + u * SUBA;
            uint32_t a_lo = a_hi + 6144;
#pragma unroll
            for (int i = 0; i < 2; i++) {
                ldsm_x4(ah[i], a_hi + aoff + i * 16 * 48);
                ldsm_x4(al[i], a_lo + aoff + i * 16 * 48);
            }
            uint32_t b_hi = sb + s * STAGE + BBASE + u * SUBB;
            uint32_t b_lo = b_hi + 4352;
#pragma unroll
            for (int j2 = 0; j2 < 4; j2++) {
                ldsm_x4_t(bh[j2], b_hi + boff + j2 * 32);
                ldsm_x4_t(bl[j2], b_lo + boff + j2 * 32);
            }
#pragma unroll
            for (int i = 0; i < 2; i++)
#pragma unroll
                for (int j = 0; j < 8; j++) {
                    const uint32_t* bph = &bh[j >> 1][(j & 1) * 2];
                    const uint32_t* bpl = &bl[j >> 1][(j & 1) * 2];
                    mma_bf16(acc[i][j], ah[i], bph);
                    mma_bf16(acc[i][j], ah[i], bpl);
                    mma_bf16(acc[i][j], al[i], bph);
                }
        }
    }

    // ---- epilogue ----
    const float* bias = g.bias[which];
    if (g.mode == 1) {
        float* C = g.c0;
#pragma unroll
        for (int i = 0; i < 2; i++) {
            int r0 = bm + wm * 32 + i * 16 + (lane >> 2);
#pragma unroll
            for (int j = 0; j < 8; j++) {
                int cc = bn + wn * 64 + j * 8 + (lane & 3) * 2;
                float b0 = bias[cc], b1 = bias[cc + 1];
                if (r0 < T_) {
                    float* p = C + (long)r0 * GN_ + cc;
                    p[0] = acc[i][j][0] + b0;
                    p[1] = acc[i][j][1] + b1;
                }
                if (r0 + 8 < T_) {
                    float* p = C + (long)(r0 + 8) * GN_ + cc;
                    p[0] = acc[i][j][2] + b0;
                    p[1] = acc[i][j][3] + b1;
                }
            }
        }
    } else {
        __nv_bfloat16* ohi = g.ohi[which];
        __nv_bfloat16* olo = g.olo[which];
        const bool dorope = (which < 2);
#pragma unroll
        for (int i = 0; i < 2; i++) {
            int r0 = bm + wm * 32 + i * 16 + (lane >> 2);
#pragma unroll
            for (int j = 0; j < 8; j++) {
                int cc = bn + wn * 64 + j * 8 + (lane & 3) * 2;
                float b0 = bias[cc], b1 = bias[cc + 1];
                int head = cc / HD_;
                int h = cc - head * HD_;
#pragma unroll
                for (int half = 0; half < 2; half++) {
                    int t = r0 + half * 8;
                    if (t >= T_) continue;
                    float v0 = acc[i][j][2 * half + 0] + b0;
                    float v1 = acc[i][j][2 * half + 1] + b1;
                    float r0v = v0, r1v = v1;
                    if (dorope) {
                        float cs = fc[t * HD_ + h];
                        float sn = fc[t * HD_ + h + 1];
                        r0v = v0 * cs - v1 * sn;
                        r1v = v0 * sn + v1 * cs;
                    }
                    uint32_t hh, ll;
                    split2(r0v, r1v, hh, ll);
                    uint32_t dst = (uint32_t)(t * NHEADS_ + head) * HP_ + h;
                    *(uint32_t*)(ohi + dst) = hh;
                    *(uint32_t*)(olo + dst) = ll;
                }
            }
        }
    }
}

// ===========================================================================
// HMMA flash attention, KV blocks of 96 keys (22 blocks over 2112 padded),
// 2-stage, ONE barrier per block. Writes hi/lo bf16 output directly.
// smem: stage s at s*79872; arrays khi/klo/vhi/vlo at +a*19968 (96 x 208 B).
// ===========================================================================
#define SSTB 208
#define KVARR 19968
#define KVSTG 79872
#define ATT_SMEM (2 * KVSTG)    // 159744
#define NBLK 22

__global__ __launch_bounds__(256, 1)
void hmma_attn_kernel(const __nv_bfloat16* __restrict__ qhi, const __nv_bfloat16* __restrict__ qlo,
                      const __nv_bfloat16* __restrict__ khi, const __nv_bfloat16* __restrict__ klo,
                      const __nv_bfloat16* __restrict__ vhi, const __nv_bfloat16* __restrict__ vlo,
                      __nv_bfloat16* __restrict__ Oh, __nv_bfloat16* __restrict__ Ol)
{
    extern __shared__ char sm[];
    uint32_t sbase = smem_u32(sm);
    const int tid = threadIdx.x;
    const int wid = tid >> 5;
    const int lane = tid & 31;
    const int n = blockIdx.y;
    const int q0 = blockIdx.x * 128;
    const float sl2 = 0.15379179f;    // 88^-0.5 * log2(e)

    // ---- stage Q (128 rows x 12 chunks, hi/lo) into low smem, read frags ----
#pragma unroll
    for (int it = 0; it < 12; it++) {
        int id = tid + it * 256;
        int arr = id / 1536;
        int rem = id - arr * 1536;
        int row = rem / 12;
        int c   = rem - row * 12;
        const __nv_bfloat16* src = (arr ? qlo : qhi) + ((long)(q0 + row) * NHEADS_ + n) * HP_ + c * 8;
        cp16(sbase + arr * 26624 + row * SSTB + c * 16, src);
    }
    CP_COMMIT();
    CP_WAIT(0);
    __syncthreads();

    uint32_t qh[6][4], ql[6][4];
    {
        uint32_t qaddr = sbase + (wid * 16 + (lane & 15)) * SSTB + (lane >> 4) * 16;
#pragma unroll
        for (int kk = 0; kk < 6; kk++) {
            ldsm_x4(qh[kk], qaddr + kk * 32);
            ldsm_x4(ql[kk], qaddr + 26624 + kk * 32);
        }
    }
    __syncthreads();   // Q frags in regs; smem free for KV

    float mstat[2] = {-1e30f, -1e30f};
    float lstat[2] = {0.f, 0.f};
    float oacc[12][4];
#pragma unroll
    for (int f = 0; f < 12; f++)
#pragma unroll
        for (int e = 0; e < 4; e++) oacc[f][e] = 0.f;

    // issue KV block 0 -> stage 0  (4 arrays x 96 rows x 12 chunks = 4608 cp)
#pragma unroll
    for (int it = 0; it < 18; it++) {
        int id = tid + it * 256;
        int arr = id / 1152;
        int rem = id - arr * 1152;
        int row = rem / 12;
        int c   = rem - row * 12;
        const __nv_bfloat16* src =
            (arr == 0 ? khi : arr == 1 ? klo : arr == 2 ? vhi : vlo)
            + ((long)row * NHEADS_ + n) * HP_ + c * 8;
        cp16(sbase + arr * KVARR + row * SSTB + c * 16, src);
    }
    CP_COMMIT();

    for (int bi = 0; bi < NBLK; bi++) {
        const int s = bi & 1;
        CP_WAIT(0);
        __syncthreads();

        if (bi + 1 < NBLK) {
            const uint32_t st = (uint32_t)((1 - s) * KVSTG);
#pragma unroll
            for (int it = 0; it < 18; it++) {
                int id = tid + it * 256;
                int arr = id / 1152;
                int rem = id - arr * 1152;
                int row = rem / 12;
                int c   = rem - row * 12;
                const __nv_bfloat16* src =
                    (arr == 0 ? khi : arr == 1 ? klo : arr == 2 ? vhi : vlo)
                    + ((long)((bi + 1) * 96 + row) * NHEADS_ + n) * HP_ + c * 8;
                cp16(sbase + st + arr * KVARR + row * SSTB + c * 16, src);
            }
            CP_COMMIT();
        }

        // ---- S = Q K^T  (12 n8-tiles over 96 keys) ----
        float sacc[12][4];
#pragma unroll
        for (int f = 0; f < 12; f++)
#pragma unroll
            for (int e = 0; e < 4; e++) sacc[f][e] = 0.f;

        uint32_t kb = sbase + s * KVSTG;
#pragma unroll
        for (int kk = 0; kk < 6; kk++) {
            uint32_t ka = kb + (lane & 15) * SSTB + (lane >> 4) * 16 + kk * 32;
#pragma unroll
            for (int j2 = 0; j2 < 6; j2++) {
                uint32_t rh[4], rl[4];
                ldsm_x4(rh, ka + j2 * (16 * SSTB));
                ldsm_x4(rl, ka + KVARR + j2 * (16 * SSTB));
                uint32_t b0h[2] = {rh[0], rh[2]}, b1h[2] = {rh[1], rh[3]};
                uint32_t b0l[2] = {rl[0], rl[2]}, b1l[2] = {rl[1], rl[3]};
                mma_bf16(sacc[2 * j2],     qh[kk], b0h);
                mma_bf16(sacc[2 * j2],     qh[kk], b0l);
                mma_bf16(sacc[2 * j2],     ql[kk], b0h);
                mma_bf16(sacc[2 * j2 + 1], qh[kk], b1h);
                mma_bf16(sacc[2 * j2 + 1], qh[kk], b1l);
                mma_bf16(sacc[2 * j2 + 1], ql[kk], b1h);
            }
        }

#pragma unroll
        for (int f = 0; f < 12; f++)
#pragma unroll
            for (int e = 0; e < 4; e++) sacc[f][e] *= sl2;
        if (bi == NBLK - 1) {
            // keys >= 2032: block starts at 2016, tiles f>=2 are padding
#pragma unroll
            for (int f = 2; f < 12; f++)
#pragma unroll
                for (int e = 0; e < 4; e++) sacc[f][e] = -1e30f;
        }

        // ---- online softmax ----
        float mxA = -1e30f, mxB = -1e30f;
#pragma unroll
        for (int f = 0; f < 12; f++) {
            mxA = fmaxf(mxA, fmaxf(sacc[f][0], sacc[f][1]));
            mxB = fmaxf(mxB, fmaxf(sacc[f][2], sacc[f][3]));
        }
        mxA = fmaxf(mxA, __shfl_xor_sync(0xffffffffu, mxA, 1));
        mxA = fmaxf(mxA, __shfl_xor_sync(0xffffffffu, mxA, 2));
        mxB = fmaxf(mxB, __shfl_xor_sync(0xffffffffu, mxB, 1));
        mxB = fmaxf(mxB, __shfl_xor_sync(0xffffffffu, mxB, 2));
        float mA = fmaxf(mstat[0], mxA);
        float mB = fmaxf(mstat[1], mxB);
        float corrA = ex2f(mstat[0] - mA);
        float corrB = ex2f(mstat[1] - mB);
        mstat[0] = mA; mstat[1] = mB;

        float rsA = 0.f, rsB = 0.f;
#pragma unroll
        for (int f = 0; f < 12; f++) {
            sacc[f][0] = ex2f(sacc[f][0] - mA);
            sacc[f][1] = ex2f(sacc[f][1] - mA);
            sacc[f][2] = ex2f(sacc[f][2] - mB);
            sacc[f][3] = ex2f(sacc[f][3] - mB);
            rsA += sacc[f][0] + sacc[f][1];
            rsB += sacc[f][2] + sacc[f][3];
        }
        rsA += __shfl_xor_sync(0xffffffffu, rsA, 1);
        rsA += __shfl_xor_sync(0xffffffffu, rsA, 2);
        rsB += __shfl_xor_sync(0xffffffffu, rsB, 1);
        rsB += __shfl_xor_sync(0xffffffffu, rsB, 2);
        lstat[0] = lstat[0] * corrA + rsA;
        lstat[1] = lstat[1] * corrB + rsB;
#pragma unroll
        for (int f = 0; f < 12; f++) {
            oacc[f][0] *= corrA; oacc[f][1] *= corrA;
            oacc[f][2] *= corrB; oacc[f][3] *= corrB;
        }

        // ---- O += P V ----
        uint32_t vbh = kb + 2 * KVARR;
#pragma unroll
        for (int kk = 0; kk < 6; kk++) {
            uint32_t phi[4], plo[4];
            split2(sacc[2 * kk][0],     sacc[2 * kk][1],     phi[0], plo[0]);
            split2(sacc[2 * kk][2],     sacc[2 * kk][3],     phi[1], plo[1]);
            split2(sacc[2 * kk + 1][0], sacc[2 * kk + 1][1], phi[2], plo[2]);
            split2(sacc[2 * kk + 1][2], sacc[2 * kk + 1][3], phi[3], plo[3]);

            uint32_t va = vbh + (kk * 16 + (lane & 15)) * SSTB + (lane >> 4) * 16;
#pragma unroll
            for (int j2 = 0; j2 < 6; j2++) {
                uint32_t th[4], tl[4];
                ldsm_x4_t(th, va + j2 * 32);
                ldsm_x4_t(tl, va + KVARR + j2 * 32);
                mma_bf16(oacc[2 * j2],     phi, &th[0]);
                mma_bf16(oacc[2 * j2],     phi, &tl[0]);
                mma_bf16(oacc[2 * j2],     plo, &th[0]);
                mma_bf16(oacc[2 * j2 + 1], phi, &th[2]);
                mma_bf16(oacc[2 * j2 + 1], phi, &tl[2]);
                mma_bf16(oacc[2 * j2 + 1], plo, &th[2]);
            }
        }
    }

    float invA = 1.f / lstat[0];
    float invB = 1.f / lstat[1];
    int rA = q0 + wid * 16 + (lane >> 2);
    int rB = rA + 8;
#pragma unroll
    for (int f = 0; f < 11; f++) {
        int h = n * HD_ + f * 8 + (lane & 3) * 2;
        uint32_t hh, ll;
        if (rA < T_) {
            split2(oacc[f][0] * invA, oacc[f][1] * invA, hh, ll);
            *(uint32_t*)(Oh + (long)rA * NH_ + h) = hh;
            *(uint32_t*)(Ol + (long)rA * NH_ + h) = ll;
        }
        if (rB < T_) {
            split2(oacc[f][2] * invB, oacc[f][3] * invB, hh, ll);
            *(uint32_t*)(Oh + (long)rB * NH_ + h) = hh;
            *(uint32_t*)(Ol + (long)rB * NH_ + h) = ll;
        }
    }
}

// ---------------------------------------------------------------------------
extern "C" void kernel_launch(void* const* d_in, const int* in_sizes, int n_in,
                              void* d_out, int out_size)
{
    const float* x  = (const float*)d_in[0];
    const float* fc = (const float*)d_in[1];
    const float* Wq = (const float*)d_in[2];
    const float* bq = (const float*)d_in[3];
    const float* Wk = (const float*)d_in[4];
    const float* bk = (const float*)d_in[5];
    const float* Wv = (const float*)d_in[6];
    const float* bv = (const float*)d_in[7];
    const float* Wo = (const float*)d_in[8];
    const float* bo = (const float*)d_in[9];
    float* out = (float*)d_out;

    __nv_bfloat16 *xh, *xl, *ah, *al, *wh, *wl;
    __nv_bfloat16 *qhi, *qlo, *khi, *klo, *vhi, *vlo;
    cudaGetSymbolAddress((void**)&xh, g_xh);
    cudaGetSymbolAddress((void**)&xl, g_xl);
    cudaGetSymbolAddress((void**)&ah, g_ah);
    cudaGetSymbolAddress((void**)&al, g_al);
    cudaGetSymbolAddress((void**)&wh, g_wh);
    cudaGetSymbolAddress((void**)&wl, g_wl);
    cudaGetSymbolAddress((void**)&qhi, g_qhi);
    cudaGetSymbolAddress((void**)&qlo, g_qlo);
    cudaGetSymbolAddress((void**)&khi, g_khi);
    cudaGetSymbolAddress((void**)&klo, g_klo);
    cudaGetSymbolAddress((void**)&vhi, g_vhi);
    cudaGetSymbolAddress((void**)&vlo, g_vlo);

    const long WSZ = (long)GK_ * GN_;
    const int n2x = T_ * GK_ / 2;
    const long n4w = 4L * WSZ / 2;

    // pad-zero + splits
    pad_kernel<<<(PAD_R1 + PAD_R2 + 255) / 256, 256>>>(qhi, qlo, khi, klo, vhi, vlo);
    split_kernel<<<(n2x + 255) / 256, 256>>>(x, xh, xl, n2x);
    wsplit_kernel<<<(int)((n4w + 255) / 256), 256>>>(Wq, Wk, Wv, Wo, wh, wl);

    cudaFuncSetAttribute(hmma_gemm4_kernel,
                         cudaFuncAttributeMaxDynamicSharedMemorySize, GEMM_SMEM);
    cudaFuncSetAttribute(hmma_attn_kernel,
                         cudaFuncAttributeMaxDynamicSharedMemorySize, ATT_SMEM);

    // fused QKV GEMM + RoPE + split + pad epilogue (grid 33x16)
    G3 gq;
    gq.bh[0] = wh + 0 * WSZ; gq.bl[0] = wl + 0 * WSZ; gq.bias[0] = bq;
    gq.bh[1] = wh + 1 * WSZ; gq.bl[1] = wl + 1 * WSZ; gq.bias[1] = bk;
    gq.bh[2] = wh + 2 * WSZ; gq.bl[2] = wl + 2 * WSZ; gq.bias[2] = bv;
    gq.ohi[0] = qhi; gq.olo[0] = qlo;
    gq.ohi[1] = khi; gq.olo[1] = klo;
    gq.ohi[2] = vhi; gq.olo[2] = vlo;
    gq.c0 = nullptr; gq.mode = 0;
    hmma_gemm4_kernel<<<dim3(33, 16), 256, GEMM_SMEM>>>(xh, xl, fc, gq);

    // HMMA flash attention -> split output
    hmma_attn_kernel<<<dim3(16, 16), 256, ATT_SMEM>>>(qhi, qlo, khi, klo,
                                                      vhi, vlo, ah, al);

    // out-proj (mode 1)
    G3 go;
    go.bh[0] = wh + 3 * WSZ; go.bl[0] = wl + 3 * WSZ; go.bias[0] = bo;
    go.bh[1] = go.bh[0]; go.bl[1] = go.bl[0]; go.bias[1] = bo;
    go.bh[2] = go.bh[0]; go.bl[2] = go.bl[0]; go.bias[2] = bo;
    go.ohi[0] = go.ohi[1] = go.ohi[2] = nullptr;
    go.olo[0] = go.olo[1] = go.olo[2] = nullptr;
    go.c0 = out; go.mode = 1;
    hmma_gemm4_kernel<<<dim3(11, 16), 256, GEMM_SMEM>>>(ah, al, fc, go);
}

// round 8
// speedup vs baseline: 1.0166x; 1.0007x over previous
#include <cuda_runtime.h>
#include <cuda_bf16.h>
#include <cstdint>
#include <math.h>

#define T_ 2032
#define TP_ 2048
#define TKV_ 2112            // keys padded to 22 * 96
#define D_ 1408
#define NH_ 1408
#define NHEADS_ 16
#define HD_ 88
#define HP_ 96
#define GK_ 1408
#define GN_ 1408
#define NC2 44               // 1408 / 32

// Scratch (allocation-free rule: device globals)
__device__ __nv_bfloat16 g_xh[T_ * GK_], g_xl[T_ * GK_];
__device__ __nv_bfloat16 g_ah[T_ * GK_], g_al[T_ * GK_];
__device__ __nv_bfloat16 g_wh[4L * GK_ * GN_], g_wl[4L * GK_ * GN_];
#define PADSZ (TKV_ * NHEADS_ * HP_)
__device__ __nv_bfloat16 g_qhi[PADSZ], g_qlo[PADSZ];
__device__ __nv_bfloat16 g_khi[PADSZ], g_klo[PADSZ];
__device__ __nv_bfloat16 g_vhi[PADSZ], g_vlo[PADSZ];

// ===========================================================================
// Helpers (baseline PTX — compute_103 safe)
// ===========================================================================
__device__ __forceinline__ uint32_t smem_u32(const void* p) {
    uint32_t a;
    asm("{ .reg .u64 t; cvta.to.shared.u64 t, %1; cvt.u32.u64 %0, t; }"
        : "=r"(a) : "l"(p));
    return a;
}
__device__ __forceinline__ void ldsm_x4(uint32_t* r, uint32_t addr) {
    asm volatile("ldmatrix.sync.aligned.m8n8.x4.shared.b16 {%0,%1,%2,%3}, [%4];"
                 : "=r"(r[0]), "=r"(r[1]), "=r"(r[2]), "=r"(r[3]) : "r"(addr));
}
__device__ __forceinline__ void ldsm_x4_t(uint32_t* r, uint32_t addr) {
    asm volatile("ldmatrix.sync.aligned.m8n8.x4.trans.shared.b16 {%0,%1,%2,%3}, [%4];"
                 : "=r"(r[0]), "=r"(r[1]), "=r"(r[2]), "=r"(r[3]) : "r"(addr));
}
__device__ __forceinline__ void mma_bf16(float* d, const uint32_t* a, const uint32_t* b) {
    asm volatile(
        "mma.sync.aligned.m16n8k16.row.col.f32.bf16.bf16.f32 "
        "{%0,%1,%2,%3}, {%4,%5,%6,%7}, {%8,%9}, {%0,%1,%2,%3};"
        : "+f"(d[0]), "+f"(d[1]), "+f"(d[2]), "+f"(d[3])
        : "r"(a[0]), "r"(a[1]), "r"(a[2]), "r"(a[3]), "r"(b[0]), "r"(b[1]));
}
__device__ __forceinline__ float ex2f(float x) {
    float y; asm("ex2.approx.f32 %0, %1;" : "=f"(y) : "f"(x)); return y;
}
__device__ __forceinline__ void cp16(uint32_t dst, const void* src) {
    asm volatile("cp.async.cg.shared.global [%0], [%1], 16;"
                 :: "r"(dst), "l"(src) : "memory");
}
__device__ __forceinline__ void cp16z(uint32_t dst, const void* src, uint32_t srcsz) {
    asm volatile("cp.async.cg.shared.global [%0], [%1], 16, %2;"
                 :: "r"(dst), "l"(src), "r"(srcsz) : "memory");
}
#define CP_COMMIT() asm volatile("cp.async.commit_group;" ::: "memory")
#define CP_WAIT(n)  asm volatile("cp.async.wait_group %0;" :: "n"(n) : "memory")

__device__ __forceinline__ void split2(float x, float y, uint32_t& h, uint32_t& l) {
    __nv_bfloat16 hx = __float2bfloat16_rn(x);
    __nv_bfloat16 hy = __float2bfloat16_rn(y);
    __nv_bfloat16 lx = __float2bfloat16_rn(x - __bfloat162float(hx));
    __nv_bfloat16 ly = __float2bfloat16_rn(y - __bfloat162float(hy));
    h = (uint32_t)__bfloat16_as_ushort(hx) | ((uint32_t)__bfloat16_as_ushort(hy) << 16);
    l = (uint32_t)__bfloat16_as_ushort(lx) | ((uint32_t)__bfloat16_as_ushort(ly) << 16);
}

// ===========================================================================
// Splits (pure bandwidth)
// ===========================================================================
__global__ void split_kernel(const float* __restrict__ src,
                             __nv_bfloat16* __restrict__ hi,
                             __nv_bfloat16* __restrict__ lo, int n2)
{
    int i = blockIdx.x * 256 + threadIdx.x;
    if (i >= n2) return;
    float2 v = ((const float2*)src)[i];
    uint32_t h, l;
    split2(v.x, v.y, h, l);
    ((uint32_t*)hi)[i] = h;
    ((uint32_t*)lo)[i] = l;
}

__global__ void wsplit_kernel(const float* __restrict__ w0, const float* __restrict__ w1,
                              const float* __restrict__ w2, const float* __restrict__ w3,
                              __nv_bfloat16* __restrict__ hi, __nv_bfloat16* __restrict__ lo)
{
    const int n2w = GK_ * GN_ / 2;
    long i = (long)blockIdx.x * 256 + threadIdx.x;
    if (i >= 4L * n2w) return;
    int which = (int)(i / n2w);
    long r = i - (long)which * n2w;
    const float* src = which == 0 ? w0 : which == 1 ? w1 : which == 2 ? w2 : w3;
    float2 v = ((const float2*)src)[r];
    uint32_t h, l;
    split2(v.x, v.y, h, l);
    ((uint32_t*)hi)[i] = h;
    ((uint32_t*)lo)[i] = l;
}

#define PAD_R1 (TKV_ * NHEADS_ * 4)
#define PAD_R2 ((TKV_ - T_) * NHEADS_ * 44)
__global__ void pad_kernel(__nv_bfloat16* a0, __nv_bfloat16* a1, __nv_bfloat16* a2,
                           __nv_bfloat16* a3, __nv_bfloat16* a4, __nv_bfloat16* a5)
{
    int i = blockIdx.x * 256 + threadIdx.x;
    uint32_t idx;
    if (i < PAD_R1) {
        int th = i >> 2, off = i & 3;
        idx = (uint32_t)th * 48 + 44 + off;
    } else if (i < PAD_R1 + PAD_R2) {
        int j = i - PAD_R1;
        int t = T_ + j / (NHEADS_ * 44);
        int r = j % (NHEADS_ * 44);
        int head = r / 44, p = r % 44;
        idx = (uint32_t)(t * NHEADS_ + head) * 48 + p;
    } else return;
    ((uint32_t*)a0)[idx] = 0; ((uint32_t*)a1)[idx] = 0;
    ((uint32_t*)a2)[idx] = 0; ((uint32_t*)a3)[idx] = 0;
    ((uint32_t*)a4)[idx] = 0; ((uint32_t*)a5)[idx] = 0;
}

// ===========================================================================
// HMMA GEMM v5: BK=32 macro-chunks, 2-stage pipeline, TERM-MAJOR MMA order
// (16 independent accumulators between dependent reuses).
// ===========================================================================
struct G3 {
    const __nv_bfloat16* bh[3];
    const __nv_bfloat16* bl[3];
    const float* bias[3];
    __nv_bfloat16* ohi[3];
    __nv_bfloat16* olo[3];
    float* c0;
    int mode;
};

#define AS_ST 24
#define BS_ST 136
#define SUBA  12288
#define SUBB  8704
#define BBASE 24576
#define STAGE 41984
#define GEMM_SMEM (2 * STAGE)   // 83968

__global__ __launch_bounds__(256, 2)
void hmma_gemm5_kernel(const __nv_bfloat16* __restrict__ Ah,
                       const __nv_bfloat16* __restrict__ Al,
                       const float* __restrict__ fc, G3 g)
{
    extern __shared__ char smg[];
    uint32_t sb = smem_u32(smg);

    const int tid = threadIdx.x;
    const int wid = tid >> 5, lane = tid & 31;
    const int wm = wid & 3, wn = wid >> 2;
    const int bm = blockIdx.y * 128;
    const int which = blockIdx.x / 11;
    const int bn = (blockIdx.x - which * 11) * 128;

    const int arow = tid >> 1;
    const int acs = (tid & 1) * 8;
    const int brow = tid >> 4;
    const int bcs = (tid & 15) * 8;
    const uint32_t aok = ((bm + arow) < T_) ? 16u : 0u;

    const __nv_bfloat16* agh = Ah + (long)(bm + arow) * GK_ + acs;
    const __nv_bfloat16* agl = Al + (long)(bm + arow) * GK_ + acs;
    const __nv_bfloat16* bgh = g.bh[which] + (long)brow * GN_ + bn + bcs;
    const __nv_bfloat16* bgl = g.bl[which] + (long)brow * GN_ + bn + bcs;

    const uint32_t as0 = sb + (arow * AS_ST + acs) * 2;
    const uint32_t bs0 = sb + BBASE + (brow * BS_ST + bcs) * 2;

    float acc[2][8][4];
#pragma unroll
    for (int i = 0; i < 2; i++)
#pragma unroll
        for (int j = 0; j < 8; j++)
#pragma unroll
            for (int e = 0; e < 4; e++) acc[i][j][e] = 0.f;

    const uint32_t aoff = (uint32_t)((wm * 32 + (lane & 15)) * 48 + (lane >> 4) * 16);
    const uint32_t boff = (uint32_t)((lane & 15) * 272 + wn * 128 + (lane >> 4) * 16);

#pragma unroll
    for (int u = 0; u < 2; u++) {
        cp16z(as0 + u * SUBA, agh + u * 16, aok);
        cp16z(as0 + u * SUBA + 6144, agl + u * 16, aok);
        cp16(bs0 + u * SUBB, bgh + (long)(u * 16) * GN_);
        cp16(bs0 + u * SUBB + 4352, bgl + (long)(u * 16) * GN_);
    }
    CP_COMMIT();

    for (int c = 0; c < NC2; c++) {
        const int s = c & 1;
        CP_WAIT(0);
        __syncthreads();

        if (c + 1 < NC2) {
            const uint32_t st = (uint32_t)((1 - s) * STAGE);
            const int k0 = (c + 1) * 32;
#pragma unroll
            for (int u = 0; u < 2; u++) {
                cp16z(as0 + st + u * SUBA, agh + k0 + u * 16, aok);
                cp16z(as0 + st + u * SUBA + 6144, agl + k0 + u * 16, aok);
                cp16(bs0 + st + u * SUBB, bgh + (long)(k0 + u * 16) * GN_);
                cp16(bs0 + st + u * SUBB + 4352, bgl + (long)(k0 + u * 16) * GN_);
            }
            CP_COMMIT();
        }

#pragma unroll
        for (int u = 0; u < 2; u++) {
            uint32_t ah[2][4], al[2][4], bh[4][4], bl[4][4];
            uint32_t a_hi = sb + s * STAGE + u * SUBA;
            uint32_t a_lo = a_hi + 6144;
#pragma unroll
            for (int i = 0; i < 2; i++) {
                ldsm_x4(ah[i], a_hi + aoff + i * 16 * 48);
                ldsm_x4(al[i], a_lo + aoff + i * 16 * 48);
            }
            uint32_t b_hi = sb + s * STAGE + BBASE + u * SUBB;
            uint32_t b_lo = b_hi + 4352;
#pragma unroll
            for (int j2 = 0; j2 < 4; j2++) {
                ldsm_x4_t(bh[j2], b_hi + boff + j2 * 32);
                ldsm_x4_t(bl[j2], b_lo + boff + j2 * 32);
            }
            // term-major: all 16 accumulators per term -> RAW distance 16
#pragma unroll
            for (int i = 0; i < 2; i++)
#pragma unroll
                for (int j = 0; j < 8; j++)
                    mma_bf16(acc[i][j], ah[i], &bh[j >> 1][(j & 1) * 2]);
#pragma unroll
            for (int i = 0; i < 2; i++)
#pragma unroll
                for (int j = 0; j < 8; j++)
                    mma_bf16(acc[i][j], ah[i], &bl[j >> 1][(j & 1) * 2]);
#pragma unroll
            for (int i = 0; i < 2; i++)
#pragma unroll
                for (int j = 0; j < 8; j++)
                    mma_bf16(acc[i][j], al[i], &bh[j >> 1][(j & 1) * 2]);
        }
    }

    // ---- epilogue ----
    const float* bias = g.bias[which];
    if (g.mode == 1) {
        float* C = g.c0;
#pragma unroll
        for (int i = 0; i < 2; i++) {
            int r0 = bm + wm * 32 + i * 16 + (lane >> 2);
#pragma unroll
            for (int j = 0; j < 8; j++) {
                int cc = bn + wn * 64 + j * 8 + (lane & 3) * 2;
                float b0 = bias[cc], b1 = bias[cc + 1];
                if (r0 < T_) {
                    float* p = C + (long)r0 * GN_ + cc;
                    p[0] = acc[i][j][0] + b0;
                    p[1] = acc[i][j][1] + b1;
                }
                if (r0 + 8 < T_) {
                    float* p = C + (long)(r0 + 8) * GN_ + cc;
                    p[0] = acc[i][j][2] + b0;
                    p[1] = acc[i][j][3] + b1;
                }
            }
        }
    } else {
        __nv_bfloat16* ohi = g.ohi[which];
        __nv_bfloat16* olo = g.olo[which];
        const bool dorope = (which < 2);
#pragma unroll
        for (int i = 0; i < 2; i++) {
            int r0 = bm + wm * 32 + i * 16 + (lane >> 2);
#pragma unroll
            for (int j = 0; j < 8; j++) {
                int cc = bn + wn * 64 + j * 8 + (lane & 3) * 2;
                float b0 = bias[cc], b1 = bias[cc + 1];
                int head = cc / HD_;
                int h = cc - head * HD_;
#pragma unroll
                for (int half = 0; half < 2; half++) {
                    int t = r0 + half * 8;
                    if (t >= T_) continue;
                    float v0 = acc[i][j][2 * half + 0] + b0;
                    float v1 = acc[i][j][2 * half + 1] + b1;
                    float r0v = v0, r1v = v1;
                    if (dorope) {
                        float cs = fc[t * HD_ + h];
                        float sn = fc[t * HD_ + h + 1];
                        r0v = v0 * cs - v1 * sn;
                        r1v = v0 * sn + v1 * cs;
                    }
                    uint32_t hh, ll;
                    split2(r0v, r1v, hh, ll);
                    uint32_t dst = (uint32_t)(t * NHEADS_ + head) * HP_ + h;
                    *(uint32_t*)(ohi + dst) = hh;
                    *(uint32_t*)(olo + dst) = ll;
                }
            }
        }
    }
}

// ===========================================================================
// HMMA flash attention, KV96 blocks, MMA loops restructured into n8-tile
// PAIRS (4 independent accumulator targets between dependent reuses).
// ===========================================================================
#define SSTB 208
#define KVARR 19968
#define KVSTG 79872
#define ATT_SMEM (2 * KVSTG)    // 159744
#define NBLK 22

__global__ __launch_bounds__(256, 1)
void hmma_attn_kernel(const __nv_bfloat16* __restrict__ qhi, const __nv_bfloat16* __restrict__ qlo,
                      const __nv_bfloat16* __restrict__ khi, const __nv_bfloat16* __restrict__ klo,
                      const __nv_bfloat16* __restrict__ vhi, const __nv_bfloat16* __restrict__ vlo,
                      __nv_bfloat16* __restrict__ Oh, __nv_bfloat16* __restrict__ Ol)
{
    extern __shared__ char sm[];
    uint32_t sbase = smem_u32(sm);
    const int tid = threadIdx.x;
    const int wid = tid >> 5;
    const int lane = tid & 31;
    const int n = blockIdx.y;
    const int q0 = blockIdx.x * 128;
    const float sl2 = 0.15379179f;    // 88^-0.5 * log2(e)

#pragma unroll
    for (int it = 0; it < 12; it++) {
        int id = tid + it * 256;
        int arr = id / 1536;
        int rem = id - arr * 1536;
        int row = rem / 12;
        int c   = rem - row * 12;
        const __nv_bfloat16* src = (arr ? qlo : qhi) + ((long)(q0 + row) * NHEADS_ + n) * HP_ + c * 8;
        cp16(sbase + arr * 26624 + row * SSTB + c * 16, src);
    }
    CP_COMMIT();
    CP_WAIT(0);
    __syncthreads();

    uint32_t qh[6][4], ql[6][4];
    {
        uint32_t qaddr = sbase + (wid * 16 + (lane & 15)) * SSTB + (lane >> 4) * 16;
#pragma unroll
        for (int kk = 0; kk < 6; kk++) {
            ldsm_x4(qh[kk], qaddr + kk * 32);
            ldsm_x4(ql[kk], qaddr + 26624 + kk * 32);
        }
    }
    __syncthreads();

    float mstat[2] = {-1e30f, -1e30f};
    float lstat[2] = {0.f, 0.f};
    float oacc[12][4];
#pragma unroll
    for (int f = 0; f < 12; f++)
#pragma unroll
        for (int e = 0; e < 4; e++) oacc[f][e] = 0.f;

#pragma unroll
    for (int it = 0; it < 18; it++) {
        int id = tid + it * 256;
        int arr = id / 1152;
        int rem = id - arr * 1152;
        int row = rem / 12;
        int c   = rem - row * 12;
        const __nv_bfloat16* src =
            (arr == 0 ? khi : arr == 1 ? klo : arr == 2 ? vhi : vlo)
            + ((long)row * NHEADS_ + n) * HP_ + c * 8;
        cp16(sbase + arr * KVARR + row * SSTB + c * 16, src);
    }
    CP_COMMIT();

    for (int bi = 0; bi < NBLK; bi++) {
        const int s = bi & 1;
        CP_WAIT(0);
        __syncthreads();

        if (bi + 1 < NBLK) {
            const uint32_t st = (uint32_t)((1 - s) * KVSTG);
#pragma unroll
            for (int it = 0; it < 18; it++) {
                int id = tid + it * 256;
                int arr = id / 1152;
                int rem = id - arr * 1152;
                int row = rem / 12;
                int c   = rem - row * 12;
                const __nv_bfloat16* src =
                    (arr == 0 ? khi : arr == 1 ? klo : arr == 2 ? vhi : vlo)
                    + ((long)((bi + 1) * 96 + row) * NHEADS_ + n) * HP_ + c * 8;
                cp16(sbase + st + arr * KVARR + row * SSTB + c * 16, src);
            }
            CP_COMMIT();
        }

        // ---- S = Q K^T : pairs of n8-tiles, term-major within pair ----
        float sacc[12][4];
#pragma unroll
        for (int f = 0; f < 12; f++)
#pragma unroll
            for (int e = 0; e < 4; e++) sacc[f][e] = 0.f;

        uint32_t kb = sbase + s * KVSTG;
#pragma unroll
        for (int kk = 0; kk < 6; kk++) {
            uint32_t ka = kb + (lane & 15) * SSTB + (lane >> 4) * 16 + kk * 32;
#pragma unroll
            for (int p = 0; p < 3; p++) {
                uint32_t rha[4], rla[4], rhb[4], rlb[4];
                ldsm_x4(rha, ka + (2 * p) * (16 * SSTB));
                ldsm_x4(rla, ka + KVARR + (2 * p) * (16 * SSTB));
                ldsm_x4(rhb, ka + (2 * p + 1) * (16 * SSTB));
                ldsm_x4(rlb, ka + KVARR + (2 * p + 1) * (16 * SSTB));
                uint32_t b0ha[2] = {rha[0], rha[2]}, b1ha[2] = {rha[1], rha[3]};
                uint32_t b0la[2] = {rla[0], rla[2]}, b1la[2] = {rla[1], rla[3]};
                uint32_t b0hb[2] = {rhb[0], rhb[2]}, b1hb[2] = {rhb[1], rhb[3]};
                uint32_t b0lb[2] = {rlb[0], rlb[2]}, b1lb[2] = {rlb[1], rlb[3]};
                float* s0 = sacc[4 * p + 0];
                float* s1 = sacc[4 * p + 1];
                float* s2 = sacc[4 * p + 2];
                float* s3 = sacc[4 * p + 3];
                mma_bf16(s0, qh[kk], b0ha); mma_bf16(s1, qh[kk], b1ha);
                mma_bf16(s2, qh[kk], b0hb); mma_bf16(s3, qh[kk], b1hb);
                mma_bf16(s0, qh[kk], b0la); mma_bf16(s1, qh[kk], b1la);
                mma_bf16(s2, qh[kk], b0lb); mma_bf16(s3, qh[kk], b1lb);
                mma_bf16(s0, ql[kk], b0ha); mma_bf16(s1, ql[kk], b1ha);
                mma_bf16(s2, ql[kk], b0hb); mma_bf16(s3, ql[kk], b1hb);
            }
        }

#pragma unroll
        for (int f = 0; f < 12; f++)
#pragma unroll
            for (int e = 0; e < 4; e++) sacc[f][e] *= sl2;
        if (bi == NBLK - 1) {
#pragma unroll
            for (int f = 2; f < 12; f++)
#pragma unroll
                for (int e = 0; e < 4; e++) sacc[f][e] = -1e30f;
        }

        // ---- online softmax ----
        float mxA = -1e30f, mxB = -1e30f;
#pragma unroll
        for (int f = 0; f < 12; f++) {
            mxA = fmaxf(mxA, fmaxf(sacc[f][0], sacc[f][1]));
            mxB = fmaxf(mxB, fmaxf(sacc[f][2], sacc[f][3]));
        }
        mxA = fmaxf(mxA, __shfl_xor_sync(0xffffffffu, mxA, 1));
        mxA = fmaxf(mxA, __shfl_xor_sync(0xffffffffu, mxA, 2));
        mxB = fmaxf(mxB, __shfl_xor_sync(0xffffffffu, mxB, 1));
        mxB = fmaxf(mxB, __shfl_xor_sync(0xffffffffu, mxB, 2));
        float mA = fmaxf(mstat[0], mxA);
        float mB = fmaxf(mstat[1], mxB);
        float corrA = ex2f(mstat[0] - mA);
        float corrB = ex2f(mstat[1] - mB);
        mstat[0] = mA; mstat[1] = mB;

        float rsA = 0.f, rsB = 0.f;
#pragma unroll
        for (int f = 0; f < 12; f++) {
            sacc[f][0] = ex2f(sacc[f][0] - mA);
            sacc[f][1] = ex2f(sacc[f][1] - mA);
            sacc[f][2] = ex2f(sacc[f][2] - mB);
            sacc[f][3] = ex2f(sacc[f][3] - mB);
            rsA += sacc[f][0] + sacc[f][1];
            rsB += sacc[f][2] + sacc[f][3];
        }
        rsA += __shfl_xor_sync(0xffffffffu, rsA, 1);
        rsA += __shfl_xor_sync(0xffffffffu, rsA, 2);
        rsB += __shfl_xor_sync(0xffffffffu, rsB, 1);
        rsB += __shfl_xor_sync(0xffffffffu, rsB, 2);
        lstat[0] = lstat[0] * corrA + rsA;
        lstat[1] = lstat[1] * corrB + rsB;
#pragma unroll
        for (int f = 0; f < 12; f++) {
            oacc[f][0] *= corrA; oacc[f][1] *= corrA;
            oacc[f][2] *= corrB; oacc[f][3] *= corrB;
        }

        // ---- O += P V : pairs of n8-tiles, term-major ----
        uint32_t vbh = kb + 2 * KVARR;
#pragma unroll
        for (int kk = 0; kk < 6; kk++) {
            uint32_t phi[4], plo[4];
            split2(sacc[2 * kk][0],     sacc[2 * kk][1],     phi[0], plo[0]);
            split2(sacc[2 * kk][2],     sacc[2 * kk][3],     phi[1], plo[1]);
            split2(sacc[2 * kk + 1][0], sacc[2 * kk + 1][1], phi[2], plo[2]);
            split2(sacc[2 * kk + 1][2], sacc[2 * kk + 1][3], phi[3], plo[3]);

            uint32_t va = vbh + (kk * 16 + (lane & 15)) * SSTB + (lane >> 4) * 16;
#pragma unroll
            for (int p = 0; p < 3; p++) {
                uint32_t tha[4], tla[4], thb[4], tlb[4];
                ldsm_x4_t(tha, va + (2 * p) * 32);
                ldsm_x4_t(tla, va + KVARR + (2 * p) * 32);
                ldsm_x4_t(thb, va + (2 * p + 1) * 32);
                ldsm_x4_t(tlb, va + KVARR + (2 * p + 1) * 32);
                float* o0 = oacc[4 * p + 0];
                float* o1 = oacc[4 * p + 1];
                float* o2 = oacc[4 * p + 2];
                float* o3 = oacc[4 * p + 3];
                mma_bf16(o0, phi, &tha[0]); mma_bf16(o1, phi, &tha[2]);
                mma_bf16(o2, phi, &thb[0]); mma_bf16(o3, phi, &thb[2]);
                mma_bf16(o0, phi, &tla[0]); mma_bf16(o1, phi, &tla[2]);
                mma_bf16(o2, phi, &tlb[0]); mma_bf16(o3, phi, &tlb[2]);
                mma_bf16(o0, plo, &tha[0]); mma_bf16(o1, plo, &tha[2]);
                mma_bf16(o2, plo, &thb[0]); mma_bf16(o3, plo, &thb[2]);
            }
        }
    }

    float invA = 1.f / lstat[0];
    float invB = 1.f / lstat[1];
    int rA = q0 + wid * 16 + (lane >> 2);
    int rB = rA + 8;
#pragma unroll
    for (int f = 0; f < 11; f++) {
        int h = n * HD_ + f * 8 + (lane & 3) * 2;
        uint32_t hh, ll;
        if (rA < T_) {
            split2(oacc[f][0] * invA, oacc[f][1] * invA, hh, ll);
            *(uint32_t*)(Oh + (long)rA * NH_ + h) = hh;
            *(uint32_t*)(Ol + (long)rA * NH_ + h) = ll;
        }
        if (rB < T_) {
            split2(oacc[f][2] * invB, oacc[f][3] * invB, hh, ll);
            *(uint32_t*)(Oh + (long)rB * NH_ + h) = hh;
            *(uint32_t*)(Ol + (long)rB * NH_ + h) = ll;
        }
    }
}

// ---------------------------------------------------------------------------
extern "C" void kernel_launch(void* const* d_in, const int* in_sizes, int n_in,
                              void* d_out, int out_size)
{
    const float* x  = (const float*)d_in[0];
    const float* fc = (const float*)d_in[1];
    const float* Wq = (const float*)d_in[2];
    const float* bq = (const float*)d_in[3];
    const float* Wk = (const float*)d_in[4];
    const float* bk = (const float*)d_in[5];
    const float* Wv = (const float*)d_in[6];
    const float* bv = (const float*)d_in[7];
    const float* Wo = (const float*)d_in[8];
    const float* bo = (const float*)d_in[9];
    float* out = (float*)d_out;

    __nv_bfloat16 *xh, *xl, *ah, *al, *wh, *wl;
    __nv_bfloat16 *qhi, *qlo, *khi, *klo, *vhi, *vlo;
    cudaGetSymbolAddress((void**)&xh, g_xh);
    cudaGetSymbolAddress((void**)&xl, g_xl);
    cudaGetSymbolAddress((void**)&ah, g_ah);
    cudaGetSymbolAddress((void**)&al, g_al);
    cudaGetSymbolAddress((void**)&wh, g_wh);
    cudaGetSymbolAddress((void**)&wl, g_wl);
    cudaGetSymbolAddress((void**)&qhi, g_qhi);
    cudaGetSymbolAddress((void**)&qlo, g_qlo);
    cudaGetSymbolAddress((void**)&khi, g_khi);
    cudaGetSymbolAddress((void**)&klo, g_klo);
    cudaGetSymbolAddress((void**)&vhi, g_vhi);
    cudaGetSymbolAddress((void**)&vlo, g_vlo);

    const long WSZ = (long)GK_ * GN_;
    const int n2x = T_ * GK_ / 2;
    const long n4w = 4L * WSZ / 2;

    pad_kernel<<<(PAD_R1 + PAD_R2 + 255) / 256, 256>>>(qhi, qlo, khi, klo, vhi, vlo);
    split_kernel<<<(n2x + 255) / 256, 256>>>(x, xh, xl, n2x);
    wsplit_kernel<<<(int)((n4w + 255) / 256), 256>>>(Wq, Wk, Wv, Wo, wh, wl);

    cudaFuncSetAttribute(hmma_gemm5_kernel,
                         cudaFuncAttributeMaxDynamicSharedMemorySize, GEMM_SMEM);
    cudaFuncSetAttribute(hmma_attn_kernel,
                         cudaFuncAttributeMaxDynamicSharedMemorySize, ATT_SMEM);

    G3 gq;
    gq.bh[0] = wh + 0 * WSZ; gq.bl[0] = wl + 0 * WSZ; gq.bias[0] = bq;
    gq.bh[1] = wh + 1 * WSZ; gq.bl[1] = wl + 1 * WSZ; gq.bias[1] = bk;
    gq.bh[2] = wh + 2 * WSZ; gq.bl[2] = wl + 2 * WSZ; gq.bias[2] = bv;
    gq.ohi[0] = qhi; gq.olo[0] = qlo;
    gq.ohi[1] = khi; gq.olo[1] = klo;
    gq.ohi[2] = vhi; gq.olo[2] = vlo;
    gq.c0 = nullptr; gq.mode = 0;
    hmma_gemm5_kernel<<<dim3(33, 16), 256, GEMM_SMEM>>>(xh, xl, fc, gq);

    hmma_attn_kernel<<<dim3(16, 16), 256, ATT_SMEM>>>(qhi, qlo, khi, klo,
                                                      vhi, vlo, ah, al);

    G3 go;
    go.bh[0] = wh + 3 * WSZ; go.bl[0] = wl + 3 * WSZ; go.bias[0] = bo;
    go.bh[1] = go.bh[0]; go.bl[1] = go.bl[0]; go.bias[1] = bo;
    go.bh[2] = go.bh[0]; go.bl[2] = go.bl[0]; go.bias[2] = bo;
    go.ohi[0] = go.ohi[1] = go.ohi[2] = nullptr;
    go.olo[0] = go.olo[1] = go.olo[2] = nullptr;
    go.c0 = out; go.mode = 1;
    hmma_gemm5_kernel<<<dim3(11, 16), 256, GEMM_SMEM>>>(ah, al, fc, go);
}